// round 4
// baseline (speedup 1.0000x reference)
#include <cuda_runtime.h>
#include <math.h>

#define BSZ 2
#define LSEQ 1024
#define DMODEL 1024
#define DINNER 2048
#define DSTATE 64
#define NHEADS 32
#define HEADDIM 64
#define CONVCH 2176
#define DPROJ 4256
#define NTOK 2048    // BSZ*LSEQ
#define SSEG 8
#define TSEG 128     // LSEQ / SSEG

typedef unsigned long long u64;
typedef unsigned int u32;

// ---------------- f32x2 packed-math helpers -----------------
__device__ __forceinline__ u64 dup2(float v) {
    u64 r; asm("mov.b64 %0, {%1, %1};" : "=l"(r) : "f"(v)); return r;
}
__device__ __forceinline__ u64 fma2(u64 a, u64 b, u64 c) {
    u64 d; asm("fma.rn.f32x2 %0, %1, %2, %3;" : "=l"(d) : "l"(a), "l"(b), "l"(c)); return d;
}
__device__ __forceinline__ u64 mul2(u64 a, u64 b) {
    u64 d; asm("mul.rn.f32x2 %0, %1, %2;" : "=l"(d) : "l"(a), "l"(b)); return d;
}
__device__ __forceinline__ void unpack2(u64 v, float& lo, float& hi) {
    asm("mov.b64 {%0, %1}, %2;" : "=f"(lo), "=f"(hi) : "l"(v));
}

// ---------------- tf32 helpers -----------------
__device__ __forceinline__ u32 to_tf32(float v) {
    u32 r; asm("cvt.rna.tf32.f32 %0, %1;" : "=r"(r) : "f"(v)); return r;
}
__device__ __forceinline__ void split_tf32(float v, u32& hi, u32& lo) {
    hi = to_tf32(v);
    lo = to_tf32(v - __uint_as_float(hi));
}
__device__ __forceinline__ void mma_tf32(float* d, const u32* a, const u32* b) {
    asm volatile(
        "mma.sync.aligned.m16n8k8.row.col.f32.tf32.tf32.f32 "
        "{%0,%1,%2,%3}, {%4,%5,%6,%7}, {%8,%9}, {%0,%1,%2,%3};"
        : "+f"(d[0]), "+f"(d[1]), "+f"(d[2]), "+f"(d[3])
        : "r"(a[0]), "r"(a[1]), "r"(a[2]), "r"(a[3]), "r"(b[0]), "r"(b[1]));
}

// ---------------- scratch ----------------
__device__ float g_zx[2][(size_t)NTOK * DPROJ];
__device__ float g_xbc[2][(size_t)NTOK * CONVCH];
__device__ float g_dt[2][NTOK * NHEADS];
__device__ float g_dA[2][NTOK * NHEADS];
__device__ float g_cump[2][NTOK * NHEADS];               // per-t within-segment cumprod of dA
__device__ float g_y[2][(size_t)NTOK * DINNER];
__device__ float g_gn[2][(size_t)NTOK * DINNER];
__device__ float g_cat[(size_t)NTOK * 2 * DMODEL];
// per (dir,b,seg,h): 64x64 state tiles
#define SEGIDX(dir,b,seg,h) ((((size_t)(dir)*BSZ + (b))*SSEG + (seg))*NHEADS + (h))
__device__ float g_hseg[2 * BSZ * SSEG * NHEADS * HEADDIM * DSTATE];  // local end states
__device__ float g_hin [2 * BSZ * SSEG * NHEADS * HEADDIM * DSTATE];  // incoming states

// ---------------- 3xTF32 tensor-core GEMM (unchanged from R3) ----------------
#define PADW 136

__global__ __launch_bounds__(256)
void tgemm(const float* __restrict__ A, int lda,
           const float* __restrict__ B, int ldb,
           float* __restrict__ C, int ldc, int c_col_off,
           int M, int N, int K, int revA, int revC,
           const float* __restrict__ bias)
{
    __shared__ float As[2][16][PADW];
    __shared__ float Bs[2][16][PADW];

    const int tid = threadIdx.x;
    const int bn = blockIdx.x * 128;
    const int bm = blockIdx.y * 128;

    const int wid = tid >> 5;
    const int lane = tid & 31;
    const int warp_m = wid >> 2;
    const int warp_n = wid & 3;
    const int g = lane >> 2;
    const int c = lane & 3;
    const int m_warp = warp_m * 64;
    const int n_warp = warp_n * 32;

    const int a_row = tid >> 1;
    const int a_col8 = (tid & 1) * 8;
    int am = bm + a_row;
    if (revA) { int bb = am >> 10; int ll = am & 1023; am = (bb << 10) + (1023 - ll); }
    const float* Aptr = A + (size_t)am * lda + a_col8;

    const int b_row = tid >> 5;
    const int b_col = (tid & 31) * 4;
    const float* Bptr = B + bn + b_col;
    const bool b_ok = (bn + b_col) < N;

    float acc[4][4][4];
#pragma unroll
    for (int i = 0; i < 4; i++)
#pragma unroll
        for (int j = 0; j < 4; j++)
#pragma unroll
            for (int r = 0; r < 4; r++) acc[i][j][r] = 0.f;

    const int nk = K / 16;

    {
        float4 pa0 = *(const float4*)(Aptr + 0);
        float4 pa1 = *(const float4*)(Aptr + 4);
        float4 pb0 = make_float4(0.f,0.f,0.f,0.f), pb1 = pb0;
        if (b_ok) {
            pb0 = *(const float4*)(Bptr + (size_t)b_row * ldb);
            pb1 = *(const float4*)(Bptr + (size_t)(b_row + 8) * ldb);
        }
        As[0][a_col8 + 0][a_row] = pa0.x; As[0][a_col8 + 1][a_row] = pa0.y;
        As[0][a_col8 + 2][a_row] = pa0.z; As[0][a_col8 + 3][a_row] = pa0.w;
        As[0][a_col8 + 4][a_row] = pa1.x; As[0][a_col8 + 5][a_row] = pa1.y;
        As[0][a_col8 + 6][a_row] = pa1.z; As[0][a_col8 + 7][a_row] = pa1.w;
        *(float4*)&Bs[0][b_row][b_col] = pb0;
        *(float4*)&Bs[0][b_row + 8][b_col] = pb1;
    }
    __syncthreads();

    for (int it = 0; it < nk; it++) {
        const int buf = it & 1;
        float4 pa0, pa1, pb0, pb1;
        const bool more = (it + 1) < nk;
        if (more) {
            int kk = (it + 1) * 16;
            pa0 = *(const float4*)(Aptr + kk);
            pa1 = *(const float4*)(Aptr + kk + 4);
            pb0 = make_float4(0.f,0.f,0.f,0.f); pb1 = pb0;
            if (b_ok) {
                pb0 = *(const float4*)(Bptr + (size_t)(kk + b_row) * ldb);
                pb1 = *(const float4*)(Bptr + (size_t)(kk + b_row + 8) * ldb);
            }
        }

#pragma unroll
        for (int ks = 0; ks < 2; ks++) {
            const int k0 = ks * 8;
            u32 bh[4][2], bl[4][2];
#pragma unroll
            for (int in = 0; in < 4; in++) {
                int n0 = n_warp + in * 8 + g;
                float v0 = Bs[buf][k0 + c][n0];
                float v1 = Bs[buf][k0 + c + 4][n0];
                split_tf32(v0, bh[in][0], bl[in][0]);
                split_tf32(v1, bh[in][1], bl[in][1]);
            }
#pragma unroll
            for (int im = 0; im < 4; im++) {
                int m0 = m_warp + im * 16 + g;
                float v0 = As[buf][k0 + c][m0];
                float v1 = As[buf][k0 + c][m0 + 8];
                float v2 = As[buf][k0 + c + 4][m0];
                float v3 = As[buf][k0 + c + 4][m0 + 8];
                u32 ah[4], al[4];
                split_tf32(v0, ah[0], al[0]);
                split_tf32(v1, ah[1], al[1]);
                split_tf32(v2, ah[2], al[2]);
                split_tf32(v3, ah[3], al[3]);
#pragma unroll
                for (int in = 0; in < 4; in++) {
                    mma_tf32(acc[im][in], ah, bh[in]);
                    mma_tf32(acc[im][in], al, bh[in]);
                    mma_tf32(acc[im][in], ah, bl[in]);
                }
            }
        }

        if (more) {
            const int nb = buf ^ 1;
            As[nb][a_col8 + 0][a_row] = pa0.x; As[nb][a_col8 + 1][a_row] = pa0.y;
            As[nb][a_col8 + 2][a_row] = pa0.z; As[nb][a_col8 + 3][a_row] = pa0.w;
            As[nb][a_col8 + 4][a_row] = pa1.x; As[nb][a_col8 + 5][a_row] = pa1.y;
            As[nb][a_col8 + 6][a_row] = pa1.z; As[nb][a_col8 + 7][a_row] = pa1.w;
            *(float4*)&Bs[nb][b_row][b_col] = pb0;
            *(float4*)&Bs[nb][b_row + 8][b_col] = pb1;
        }
        __syncthreads();
    }

#pragma unroll
    for (int im = 0; im < 4; im++) {
        int mrow0 = bm + m_warp + im * 16 + g;
        int mrow1 = mrow0 + 8;
        int w0 = mrow0, w1 = mrow1;
        if (revC) {
            int bb = mrow0 >> 10, ll = mrow0 & 1023; w0 = (bb << 10) + (1023 - ll);
            bb = mrow1 >> 10; ll = mrow1 & 1023; w1 = (bb << 10) + (1023 - ll);
        }
        float* C0 = C + (size_t)w0 * ldc + c_col_off;
        float* C1 = C + (size_t)w1 * ldc + c_col_off;
#pragma unroll
        for (int in = 0; in < 4; in++) {
            int n0 = bn + n_warp + in * 8 + c * 2;
            float b0 = 0.f, b1 = 0.f;
            if (bias) {
                if (n0 < N) b0 = bias[n0];
                if (n0 + 1 < N) b1 = bias[n0 + 1];
            }
            if (n0 < N)     { C0[n0]     = acc[im][in][0] + b0; }
            if (n0 + 1 < N) { C0[n0 + 1] = acc[im][in][1] + b1; }
            if (n0 < N)     { C1[n0]     = acc[im][in][2] + b0; }
            if (n0 + 1 < N) { C1[n0 + 1] = acc[im][in][3] + b1; }
        }
    }
}

// ---------------- conv (causal depthwise, 4 taps) + silu + dt/dA --------------
__global__ __launch_bounds__(256)
void conv_silu_dt(const float* __restrict__ cw0, const float* __restrict__ cb0,
                  const float* __restrict__ dtb0, const float* __restrict__ Al0,
                  const float* __restrict__ cw1, const float* __restrict__ cb1,
                  const float* __restrict__ dtb1, const float* __restrict__ Al1)
{
    const int dir = blockIdx.z;
    const int b = blockIdx.y;
    const int l = blockIdx.x;
    const float* cw  = dir ? cw1  : cw0;
    const float* cb  = dir ? cb1  : cb0;
    const float* dtb = dir ? dtb1 : dtb0;
    const float* Al  = dir ? Al1  : Al0;

    const float* zx = g_zx[dir];
    const int row = b * LSEQ + l;
    float* out = g_xbc[dir] + (size_t)row * CONVCH;

    for (int c = threadIdx.x; c < CONVCH; c += 256) {
        float acc = cb[c];
#pragma unroll
        for (int j = 0; j < 4; j++) {
            int ls = l - 3 + j;
            if (ls >= 0)
                acc = fmaf(cw[j * CONVCH + c],
                           zx[(size_t)(b * LSEQ + ls) * DPROJ + DINNER + c], acc);
        }
        out[c] = acc * (1.f / (1.f + expf(-acc)));
    }

    for (int h = threadIdx.x; h < NHEADS; h += 256) {
        float v = zx[(size_t)row * DPROJ + DINNER + CONVCH + h] + dtb[h];
        float dt = (v > 20.f) ? v : log1pf(expf(v));
        g_dt[dir][row * NHEADS + h] = dt;
        g_dA[dir][row * NHEADS + h] = expf(-expf(Al[h]) * dt);
    }
}

// ---------------- pass A: local scans per 128-step segment --------------------
// grid = (NHEADS, BSZ*SSEG, 2); block 256: thread t -> p=t>>2, n0=(t&3)*16
#define TCHUNK 16
__global__ __launch_bounds__(256)
void scan_local(const float* __restrict__ D0, const float* __restrict__ D1)
{
    const int h = blockIdx.x;
    const int b = blockIdx.y / SSEG;
    const int seg = blockIdx.y % SSEG;
    const int dir = blockIdx.z;
    const float* xbc = g_xbc[dir];
    const float* dtp = g_dt[dir];
    const float* dAp = g_dA[dir];
    float* cmp = g_cump[dir];
    float* yout = g_y[dir];
    const float Dh = (dir ? D1 : D0)[h];

    __shared__ float Bs[TCHUNK][DSTATE];
    __shared__ float Cs[TCHUNK][DSTATE];
    __shared__ float Xs[TCHUNK][HEADDIM];
    __shared__ float dAs[TCHUNK], dts[TCHUNK];

    const int tid = threadIdx.x;
    const int p = tid >> 2;
    const int q = tid & 3;
    const int n0 = q * 16;

    u64 hs2[8];
#pragma unroll
    for (int i = 0; i < 8; i++) hs2[i] = 0ull;
    float cp = 1.f;

    const int t0 = b * LSEQ + seg * TSEG;
    for (int l0 = 0; l0 < TSEG; l0 += TCHUNK) {
        for (int i = tid; i < TCHUNK * 64; i += 256) {
            int tt = i >> 6, j = i & 63;
            size_t r = (size_t)(t0 + l0 + tt);
            Bs[tt][j] = xbc[r * CONVCH + DINNER + j];
            Cs[tt][j] = xbc[r * CONVCH + DINNER + DSTATE + j];
            Xs[tt][j] = xbc[r * CONVCH + h * HEADDIM + j];
        }
        if (tid < TCHUNK) {
            size_t r = (size_t)(t0 + l0 + tid);
            dAs[tid] = dAp[r * NHEADS + h];
            dts[tid] = dtp[r * NHEADS + h];
        }
        __syncthreads();

#pragma unroll
        for (int tt = 0; tt < TCHUNK; tt++) {
            float xp = Xs[tt][p];
            float da = dAs[tt];
            u64 da2 = dup2(da);
            u64 coef2 = dup2(dts[tt] * xp);
            u64 ya = 0ull, yb = 0ull;
            const u64* Bv = (const u64*)&Bs[tt][n0];
            const u64* Cv = (const u64*)&Cs[tt][n0];
#pragma unroll
            for (int i = 0; i < 8; i += 2) {
                hs2[i]   = fma2(da2, hs2[i],   mul2(coef2, Bv[i]));
                ya = fma2(Cv[i],   hs2[i],   ya);
                hs2[i+1] = fma2(da2, hs2[i+1], mul2(coef2, Bv[i+1]));
                yb = fma2(Cv[i+1], hs2[i+1], yb);
            }
            cp *= da;
            float ylo, yhi, ylo2, yhi2;
            unpack2(ya, ylo, yhi);
            unpack2(yb, ylo2, yhi2);
            float ysum = (ylo + yhi) + (ylo2 + yhi2);
            ysum += __shfl_xor_sync(0xffffffffu, ysum, 1);
            ysum += __shfl_xor_sync(0xffffffffu, ysum, 2);
            if (q == 0)
                yout[(size_t)(t0 + l0 + tt) * DINNER + h * HEADDIM + p] =
                    ysum + Dh * xp;
            if (tid == 0)
                cmp[(size_t)(t0 + l0 + tt) * NHEADS + h] = cp;
        }
        __syncthreads();
    }

    // write local end state
    float* hdst = g_hseg + SEGIDX(dir, b, seg, h) * (HEADDIM * DSTATE) + p * DSTATE + n0;
#pragma unroll
    for (int i = 0; i < 8; i++) ((u64*)hdst)[i] = hs2[i];
}

// ---------------- pass B: combine segment boundary states ---------------------
// grid = (NHEADS, BSZ, 2); block 256
__global__ __launch_bounds__(256)
void seg_combine()
{
    const int h = blockIdx.x;
    const int b = blockIdx.y;
    const int dir = blockIdx.z;
    const int tid = threadIdx.x;
    const int p = tid >> 2;
    const int n0 = (tid & 3) * 16;
    const int off = p * DSTATE + n0;

    float hr[16];
#pragma unroll
    for (int i = 0; i < 16; i++) hr[i] = 0.f;

    for (int seg = 0; seg < SSEG; seg++) {
        size_t base = SEGIDX(dir, b, seg, h) * (size_t)(HEADDIM * DSTATE) + off;
        float* hin = g_hin + base;
#pragma unroll
        for (int i = 0; i < 16; i++) hin[i] = hr[i];
        float Pseg = g_cump[dir][(size_t)(b * LSEQ + seg * TSEG + TSEG - 1) * NHEADS + h];
        const float* hend = g_hseg + base;
#pragma unroll
        for (int i = 0; i < 16; i++) hr[i] = fmaf(Pseg, hr[i], hend[i]);
    }
}

// ---------------- pass C: t-parallel cross-segment correction -----------------
// y[t,p] += P_t * sum_n C[t,n] * h_in[p,n];  grid = (NHEADS, BSZ*SSEG, 2)
__global__ __launch_bounds__(256)
void seg_correct()
{
    const int h = blockIdx.x;
    const int b = blockIdx.y / SSEG;
    const int seg = blockIdx.y % SSEG;
    if (seg == 0) return;
    const int dir = blockIdx.z;
    const float* xbc = g_xbc[dir];
    const float* cmp = g_cump[dir];
    float* yout = g_y[dir];

    __shared__ float Cs[TCHUNK][DSTATE];
    __shared__ float cps[TCHUNK];

    const int tid = threadIdx.x;
    const int p = tid >> 2;
    const int q = tid & 3;
    const int n0 = q * 16;

    // load this thread's slice of h_in
    const float* hin = g_hin + SEGIDX(dir, b, seg, h) * (size_t)(HEADDIM * DSTATE)
                       + p * DSTATE + n0;
    u64 hv[8];
#pragma unroll
    for (int i = 0; i < 8; i++) hv[i] = ((const u64*)hin)[i];

    const int t0 = b * LSEQ + seg * TSEG;
    for (int l0 = 0; l0 < TSEG; l0 += TCHUNK) {
        for (int i = tid; i < TCHUNK * 64; i += 256) {
            int tt = i >> 6, j = i & 63;
            size_t r = (size_t)(t0 + l0 + tt);
            Cs[tt][j] = xbc[r * CONVCH + DINNER + DSTATE + j];
        }
        if (tid < TCHUNK)
            cps[tid] = cmp[(size_t)(t0 + l0 + tid) * NHEADS + h];
        __syncthreads();

#pragma unroll
        for (int tt = 0; tt < TCHUNK; tt++) {
            const u64* Cv = (const u64*)&Cs[tt][n0];
            u64 ya = 0ull, yb = 0ull;
#pragma unroll
            for (int i = 0; i < 8; i += 2) {
                ya = fma2(Cv[i],   hv[i],   ya);
                yb = fma2(Cv[i+1], hv[i+1], yb);
            }
            float ylo, yhi, ylo2, yhi2;
            unpack2(ya, ylo, yhi);
            unpack2(yb, ylo2, yhi2);
            float dot = (ylo + yhi) + (ylo2 + yhi2);
            dot += __shfl_xor_sync(0xffffffffu, dot, 1);
            dot += __shfl_xor_sync(0xffffffffu, dot, 2);
            if (q == 0) {
                size_t idx = (size_t)(t0 + l0 + tt) * DINNER + h * HEADDIM + p;
                yout[idx] = fmaf(cps[tt], dot, yout[idx]);
            }
        }
        __syncthreads();
    }
}

// ---------------- gated RMSNorm ----------------
__global__ __launch_bounds__(256)
void gated_norm(const float* __restrict__ nw0, const float* __restrict__ nw1)
{
    const int dir = blockIdx.y;
    const int row = blockIdx.x;
    const float* nw = dir ? nw1 : nw0;
    const float* y = g_y[dir] + (size_t)row * DINNER;
    const float* z = g_zx[dir] + (size_t)row * DPROJ;
    float* o = g_gn[dir] + (size_t)row * DINNER;

    float vals[8];
    float ss = 0.f;
#pragma unroll
    for (int i = 0; i < 8; i++) {
        int c = threadIdx.x + i * 256;
        float zz = z[c];
        float g = y[c] * (zz / (1.f + expf(-zz)));
        vals[i] = g;
        ss = fmaf(g, g, ss);
    }
#pragma unroll
    for (int o2 = 16; o2; o2 >>= 1) ss += __shfl_xor_sync(0xffffffffu, ss, o2);
    __shared__ float red[8];
    if ((threadIdx.x & 31) == 0) red[threadIdx.x >> 5] = ss;
    __syncthreads();
    float tot = red[0] + red[1] + red[2] + red[3] + red[4] + red[5] + red[6] + red[7];
    float scale = rsqrtf(tot * (1.f / DINNER) + 1e-5f);
#pragma unroll
    for (int i = 0; i < 8; i++) {
        int c = threadIdx.x + i * 256;
        o[c] = vals[i] * scale * nw[c];
    }
}

// ---------------- launch ----------------
extern "C" void kernel_launch(void* const* d_in, const int* in_sizes, int n_in,
                              void* d_out, int out_size)
{
    (void)in_sizes; (void)n_in; (void)out_size;
    const float* x      = (const float*)d_in[0];
    const float* fWin   = (const float*)d_in[1];
    const float* fconvw = (const float*)d_in[2];
    const float* fconvb = (const float*)d_in[3];
    const float* fdtb   = (const float*)d_in[4];
    const float* fAlog  = (const float*)d_in[5];
    const float* fD     = (const float*)d_in[6];
    const float* fnormw = (const float*)d_in[7];
    const float* fWout  = (const float*)d_in[8];
    const float* bWin   = (const float*)d_in[9];
    const float* bconvw = (const float*)d_in[10];
    const float* bconvb = (const float*)d_in[11];
    const float* bdtb   = (const float*)d_in[12];
    const float* bAlog  = (const float*)d_in[13];
    const float* bD     = (const float*)d_in[14];
    const float* bnormw = (const float*)d_in[15];
    const float* bWout  = (const float*)d_in[16];
    const float* Wo     = (const float*)d_in[17];
    const float* bo     = (const float*)d_in[18];
    float* out = (float*)d_out;

    float *zx, *gn, *cat;
    cudaGetSymbolAddress((void**)&zx, g_zx);
    cudaGetSymbolAddress((void**)&gn, g_gn);
    cudaGetSymbolAddress((void**)&cat, g_cat);
    float* zx0 = zx;
    float* zx1 = zx + (size_t)NTOK * DPROJ;
    float* gn0 = gn;
    float* gn1 = gn + (size_t)NTOK * DINNER;

    // 1) input projections
    dim3 g1((DPROJ + 127) / 128, NTOK / 128);
    tgemm<<<g1, 256>>>(x, DMODEL, fWin, DPROJ, zx0, DPROJ, 0,
                       NTOK, DPROJ, DMODEL, 0, 0, nullptr);
    tgemm<<<g1, 256>>>(x, DMODEL, bWin, DPROJ, zx1, DPROJ, 0,
                       NTOK, DPROJ, DMODEL, 1, 0, nullptr);

    // 2) causal conv + silu + dt/dA
    conv_silu_dt<<<dim3(LSEQ, BSZ, 2), 256>>>(fconvw, fconvb, fdtb, fAlog,
                                              bconvw, bconvb, bdtb, bAlog);

    // 3) segment-parallel selective scan
    scan_local<<<dim3(NHEADS, BSZ * SSEG, 2), 256>>>(fD, bD);
    seg_combine<<<dim3(NHEADS, BSZ, 2), 256>>>();
    seg_correct<<<dim3(NHEADS, BSZ * SSEG, 2), 256>>>();

    // 4) gated RMSNorm
    gated_norm<<<dim3(NTOK, 2), 256>>>(fnormw, bnormw);

    // 5) per-direction output projections
    dim3 g2(DMODEL / 128, NTOK / 128);
    tgemm<<<g2, 256>>>(gn0, DINNER, fWout, DMODEL, cat, 2 * DMODEL, 0,
                       NTOK, DMODEL, DINNER, 0, 0, nullptr);
    tgemm<<<g2, 256>>>(gn1, DINNER, bWout, DMODEL, cat, 2 * DMODEL, DMODEL,
                       NTOK, DMODEL, DINNER, 0, 1, nullptr);

    // 6) final projection + bias
    tgemm<<<g2, 256>>>(cat, 2 * DMODEL, Wo, DMODEL, out, DMODEL, 0,
                       NTOK, DMODEL, 2 * DMODEL, 0, 0, bo);
}

// round 5
// speedup vs baseline: 1.2195x; 1.2195x over previous
#include <cuda_runtime.h>
#include <math.h>

#define BSZ 2
#define LSEQ 1024
#define DMODEL 1024
#define DINNER 2048
#define DSTATE 64
#define NHEADS 32
#define HEADDIM 64
#define CONVCH 2176
#define DPROJ 4256
#define NTOK 2048    // BSZ*LSEQ
#define SSEG 16      // chunks per sequence
#define TSEG 64      // chunk length

typedef unsigned long long u64;
typedef unsigned int u32;

// ---------------- tf32 helpers -----------------
__device__ __forceinline__ u32 to_tf32(float v) {
    u32 r; asm("cvt.rna.tf32.f32 %0, %1;" : "=r"(r) : "f"(v)); return r;
}
__device__ __forceinline__ void split_tf32(float v, u32& hi, u32& lo) {
    hi = to_tf32(v);
    lo = to_tf32(v - __uint_as_float(hi));
}
__device__ __forceinline__ void mma_tf32(float* d, const u32* a, const u32* b) {
    asm volatile(
        "mma.sync.aligned.m16n8k8.row.col.f32.tf32.tf32.f32 "
        "{%0,%1,%2,%3}, {%4,%5,%6,%7}, {%8,%9}, {%0,%1,%2,%3};"
        : "+f"(d[0]), "+f"(d[1]), "+f"(d[2]), "+f"(d[3])
        : "r"(a[0]), "r"(a[1]), "r"(a[2]), "r"(a[3]), "r"(b[0]), "r"(b[1]));
}

// ---------------- scratch ----------------
__device__ float g_zx[2][(size_t)NTOK * DPROJ];
__device__ float g_xbc[2][(size_t)NTOK * CONVCH];
__device__ float g_dt[2][NTOK * NHEADS];
__device__ float g_dA[2][NTOK * NHEADS];
__device__ float g_cump[2][NTOK * NHEADS];   // ahat: within-chunk inclusive cumprod of dA
__device__ float g_y[2][(size_t)NTOK * DINNER];
__device__ float g_gn[2][(size_t)NTOK * DINNER];
__device__ float g_cat[(size_t)NTOK * 2 * DMODEL];
#define SEGIDX(dir,b,seg,h) ((((size_t)(dir)*BSZ + (b))*SSEG + (seg))*NHEADS + (h))
__device__ float g_hseg[(size_t)2 * BSZ * SSEG * NHEADS * HEADDIM * DSTATE]; // local end states [n][p]
__device__ float g_hin [(size_t)2 * BSZ * SSEG * NHEADS * HEADDIM * DSTATE]; // incoming states [n][p]

// ---------------- 3xTF32 tensor-core GEMM (projections) ----------------
#define PADW 136

__global__ __launch_bounds__(256)
void tgemm(const float* __restrict__ A, int lda,
           const float* __restrict__ B, int ldb,
           float* __restrict__ C, int ldc, int c_col_off,
           int M, int N, int K, int revA, int revC,
           const float* __restrict__ bias)
{
    __shared__ float As[2][16][PADW];
    __shared__ float Bs[2][16][PADW];

    const int tid = threadIdx.x;
    const int bn = blockIdx.x * 128;
    const int bm = blockIdx.y * 128;

    const int wid = tid >> 5;
    const int lane = tid & 31;
    const int warp_m = wid >> 2;
    const int warp_n = wid & 3;
    const int g = lane >> 2;
    const int c = lane & 3;
    const int m_warp = warp_m * 64;
    const int n_warp = warp_n * 32;

    const int a_row = tid >> 1;
    const int a_col8 = (tid & 1) * 8;
    int am = bm + a_row;
    if (revA) { int bb = am >> 10; int ll = am & 1023; am = (bb << 10) + (1023 - ll); }
    const float* Aptr = A + (size_t)am * lda + a_col8;

    const int b_row = tid >> 5;
    const int b_col = (tid & 31) * 4;
    const float* Bptr = B + bn + b_col;
    const bool b_ok = (bn + b_col) < N;

    float acc[4][4][4];
#pragma unroll
    for (int i = 0; i < 4; i++)
#pragma unroll
        for (int j = 0; j < 4; j++)
#pragma unroll
            for (int r = 0; r < 4; r++) acc[i][j][r] = 0.f;

    const int nk = K / 16;

    {
        float4 pa0 = *(const float4*)(Aptr + 0);
        float4 pa1 = *(const float4*)(Aptr + 4);
        float4 pb0 = make_float4(0.f,0.f,0.f,0.f), pb1 = pb0;
        if (b_ok) {
            pb0 = *(const float4*)(Bptr + (size_t)b_row * ldb);
            pb1 = *(const float4*)(Bptr + (size_t)(b_row + 8) * ldb);
        }
        As[0][a_col8 + 0][a_row] = pa0.x; As[0][a_col8 + 1][a_row] = pa0.y;
        As[0][a_col8 + 2][a_row] = pa0.z; As[0][a_col8 + 3][a_row] = pa0.w;
        As[0][a_col8 + 4][a_row] = pa1.x; As[0][a_col8 + 5][a_row] = pa1.y;
        As[0][a_col8 + 6][a_row] = pa1.z; As[0][a_col8 + 7][a_row] = pa1.w;
        *(float4*)&Bs[0][b_row][b_col] = pb0;
        *(float4*)&Bs[0][b_row + 8][b_col] = pb1;
    }
    __syncthreads();

    for (int it = 0; it < nk; it++) {
        const int buf = it & 1;
        float4 pa0, pa1, pb0, pb1;
        const bool more = (it + 1) < nk;
        if (more) {
            int kk = (it + 1) * 16;
            pa0 = *(const float4*)(Aptr + kk);
            pa1 = *(const float4*)(Aptr + kk + 4);
            pb0 = make_float4(0.f,0.f,0.f,0.f); pb1 = pb0;
            if (b_ok) {
                pb0 = *(const float4*)(Bptr + (size_t)(kk + b_row) * ldb);
                pb1 = *(const float4*)(Bptr + (size_t)(kk + b_row + 8) * ldb);
            }
        }

#pragma unroll
        for (int ks = 0; ks < 2; ks++) {
            const int k0 = ks * 8;
            u32 bh[4][2], bl[4][2];
#pragma unroll
            for (int in = 0; in < 4; in++) {
                int n0 = n_warp + in * 8 + g;
                float v0 = Bs[buf][k0 + c][n0];
                float v1 = Bs[buf][k0 + c + 4][n0];
                split_tf32(v0, bh[in][0], bl[in][0]);
                split_tf32(v1, bh[in][1], bl[in][1]);
            }
#pragma unroll
            for (int im = 0; im < 4; im++) {
                int m0 = m_warp + im * 16 + g;
                float v0 = As[buf][k0 + c][m0];
                float v1 = As[buf][k0 + c][m0 + 8];
                float v2 = As[buf][k0 + c + 4][m0];
                float v3 = As[buf][k0 + c + 4][m0 + 8];
                u32 ah[4], al[4];
                split_tf32(v0, ah[0], al[0]);
                split_tf32(v1, ah[1], al[1]);
                split_tf32(v2, ah[2], al[2]);
                split_tf32(v3, ah[3], al[3]);
#pragma unroll
                for (int in = 0; in < 4; in++) {
                    mma_tf32(acc[im][in], ah, bh[in]);
                    mma_tf32(acc[im][in], al, bh[in]);
                    mma_tf32(acc[im][in], ah, bl[in]);
                }
            }
        }

        if (more) {
            const int nb = buf ^ 1;
            As[nb][a_col8 + 0][a_row] = pa0.x; As[nb][a_col8 + 1][a_row] = pa0.y;
            As[nb][a_col8 + 2][a_row] = pa0.z; As[nb][a_col8 + 3][a_row] = pa0.w;
            As[nb][a_col8 + 4][a_row] = pa1.x; As[nb][a_col8 + 5][a_row] = pa1.y;
            As[nb][a_col8 + 6][a_row] = pa1.z; As[nb][a_col8 + 7][a_row] = pa1.w;
            *(float4*)&Bs[nb][b_row][b_col] = pb0;
            *(float4*)&Bs[nb][b_row + 8][b_col] = pb1;
        }
        __syncthreads();
    }

#pragma unroll
    for (int im = 0; im < 4; im++) {
        int mrow0 = bm + m_warp + im * 16 + g;
        int mrow1 = mrow0 + 8;
        int w0 = mrow0, w1 = mrow1;
        if (revC) {
            int bb = mrow0 >> 10, ll = mrow0 & 1023; w0 = (bb << 10) + (1023 - ll);
            bb = mrow1 >> 10; ll = mrow1 & 1023; w1 = (bb << 10) + (1023 - ll);
        }
        float* C0 = C + (size_t)w0 * ldc + c_col_off;
        float* C1 = C + (size_t)w1 * ldc + c_col_off;
#pragma unroll
        for (int in = 0; in < 4; in++) {
            int n0 = bn + n_warp + in * 8 + c * 2;
            float b0 = 0.f, b1 = 0.f;
            if (bias) {
                if (n0 < N) b0 = bias[n0];
                if (n0 + 1 < N) b1 = bias[n0 + 1];
            }
            if (n0 < N)     { C0[n0]     = acc[im][in][0] + b0; }
            if (n0 + 1 < N) { C0[n0 + 1] = acc[im][in][1] + b1; }
            if (n0 < N)     { C1[n0]     = acc[im][in][2] + b0; }
            if (n0 + 1 < N) { C1[n0 + 1] = acc[im][in][3] + b1; }
        }
    }
}

// ---------------- conv (causal depthwise, 4 taps) + silu + dt/dA --------------
__global__ __launch_bounds__(256)
void conv_silu_dt(const float* __restrict__ cw0, const float* __restrict__ cb0,
                  const float* __restrict__ dtb0, const float* __restrict__ Al0,
                  const float* __restrict__ cw1, const float* __restrict__ cb1,
                  const float* __restrict__ dtb1, const float* __restrict__ Al1)
{
    const int dir = blockIdx.z;
    const int b = blockIdx.y;
    const int l = blockIdx.x;
    const float* cw  = dir ? cw1  : cw0;
    const float* cb  = dir ? cb1  : cb0;
    const float* dtb = dir ? dtb1 : dtb0;
    const float* Al  = dir ? Al1  : Al0;

    const float* zx = g_zx[dir];
    const int row = b * LSEQ + l;
    float* out = g_xbc[dir] + (size_t)row * CONVCH;

    for (int c = threadIdx.x; c < CONVCH; c += 256) {
        float acc = cb[c];
#pragma unroll
        for (int j = 0; j < 4; j++) {
            int ls = l - 3 + j;
            if (ls >= 0)
                acc = fmaf(cw[j * CONVCH + c],
                           zx[(size_t)(b * LSEQ + ls) * DPROJ + DINNER + c], acc);
        }
        out[c] = acc * (1.f / (1.f + expf(-acc)));
    }

    for (int h = threadIdx.x; h < NHEADS; h += 256) {
        float v = zx[(size_t)row * DPROJ + DINNER + CONVCH + h] + dtb[h];
        float dt = (v > 20.f) ? v : log1pf(expf(v));
        g_dt[dir][row * NHEADS + h] = dt;
        g_dA[dir][row * NHEADS + h] = expf(-expf(Al[h]) * dt);
    }
}

// ---------------- warp-level 64x64x64 3xTF32 GEMM helper ----------------
// A element (m,k): AK ? As[k*72+m] : As[m*72+k]
// B element (k,n): BK ? Bm[k*72+n] : Bm[n*72+k]
// warp covers rows [m0,m0+16), cols [n0w, n0w+32). acc[4 nfrag][4].
template<int AK, int BK>
__device__ __forceinline__ void wgemm64(float (*acc)[4], const float* As, const float* Bm,
                                        int m0, int n0w, int fg, int fc)
{
#pragma unroll
    for (int k0 = 0; k0 < 64; k0 += 8) {
        u32 bh[4][2], bl[4][2];
#pragma unroll
        for (int in = 0; in < 4; in++) {
            int n = n0w + in * 8 + fg;
            float v0 = BK ? Bm[(k0 + fc) * 72 + n]     : Bm[n * 72 + k0 + fc];
            float v1 = BK ? Bm[(k0 + fc + 4) * 72 + n] : Bm[n * 72 + k0 + fc + 4];
            split_tf32(v0, bh[in][0], bl[in][0]);
            split_tf32(v1, bh[in][1], bl[in][1]);
        }
        float av0 = AK ? As[(k0 + fc) * 72 + m0 + fg]       : As[(m0 + fg) * 72 + k0 + fc];
        float av1 = AK ? As[(k0 + fc) * 72 + m0 + fg + 8]   : As[(m0 + fg + 8) * 72 + k0 + fc];
        float av2 = AK ? As[(k0 + fc + 4) * 72 + m0 + fg]   : As[(m0 + fg) * 72 + k0 + fc + 4];
        float av3 = AK ? As[(k0 + fc + 4) * 72 + m0 + fg + 8] : As[(m0 + fg + 8) * 72 + k0 + fc + 4];
        u32 ah[4], al[4];
        split_tf32(av0, ah[0], al[0]);
        split_tf32(av1, ah[1], al[1]);
        split_tf32(av2, ah[2], al[2]);
        split_tf32(av3, ah[3], al[3]);
#pragma unroll
        for (int in = 0; in < 4; in++) {
            mma_tf32(acc[in], ah, bh[in]);
            mma_tf32(acc[in], al, bh[in]);
            mma_tf32(acc[in], ah, bl[in]);
        }
    }
}

// ---------------- SSD pass 1: per-chunk local end state + cumprods ------------
// h_end[n,p] = sum_s (w[s]*B[s,n]) * x[s,p];  w[s] = dt_s * prod_{i>s} dA_i
__global__ __launch_bounds__(256)
void ssd_state()
{
    const int h = blockIdx.x;
    const int b = blockIdx.y / SSEG;
    const int ch = blockIdx.y % SSEG;
    const int dir = blockIdx.z;
    const int tid = threadIdx.x;
    const int t0 = b * LSEQ + ch * TSEG;
    const float* xbc = g_xbc[dir];

    __shared__ float Bs[64 * 72];
    __shared__ float Xs[64 * 72];
    __shared__ float das[64], dts_[64], w_[64], ahat_[64];

    for (int i = tid; i < 1024; i += 256) {
        int r = i >> 4, c4 = (i & 15) * 4;
        size_t row = (size_t)(t0 + r) * CONVCH;
        *(float4*)&Bs[r * 72 + c4] = *(const float4*)&xbc[row + DINNER + c4];
        *(float4*)&Xs[r * 72 + c4] = *(const float4*)&xbc[row + h * HEADDIM + c4];
    }
    if (tid < 64) {
        das[tid]  = g_dA[dir][(size_t)(t0 + tid) * NHEADS + h];
        dts_[tid] = g_dt[dir][(size_t)(t0 + tid) * NHEADS + h];
    }
    __syncthreads();
    if (tid == 0) {
        float acc = 1.f;
        for (int t = 0; t < 64; t++) { acc *= das[t]; ahat_[t] = acc; }
        float suf = 1.f;
        for (int s = 63; s >= 0; s--) { w_[s] = dts_[s] * suf; suf *= das[s]; }
    }
    __syncthreads();
    if (tid < 64)
        g_cump[dir][(size_t)(t0 + tid) * NHEADS + h] = ahat_[tid];
    for (int i = tid; i < 4096; i += 256) {
        int s = i >> 6, n = i & 63;
        Bs[s * 72 + n] *= w_[s];
    }
    __syncthreads();

    const int wid = tid >> 5, lane = tid & 31, fg = lane >> 2, fc = lane & 3;
    const int m0 = (wid & 3) * 16, n0w = (wid >> 2) * 32;
    float acc[4][4];
#pragma unroll
    for (int i = 0; i < 4; i++)
#pragma unroll
        for (int j = 0; j < 4; j++) acc[i][j] = 0.f;
    wgemm64<1, 1>(acc, Bs, Xs, m0, n0w, fg, fc);

    float* hd = g_hseg + SEGIDX(dir, b, ch, h) * (size_t)(HEADDIM * DSTATE);
#pragma unroll
    for (int in = 0; in < 4; in++) {
        int p = n0w + in * 8 + 2 * fc;
        hd[(m0 + fg) * 64 + p]     = acc[in][0];
        hd[(m0 + fg) * 64 + p + 1] = acc[in][1];
        hd[(m0 + fg + 8) * 64 + p]     = acc[in][2];
        hd[(m0 + fg + 8) * 64 + p + 1] = acc[in][3];
    }
}

// ---------------- SSD pass 2: combine chunk boundary states -------------------
__global__ __launch_bounds__(256)
void ssd_combine()
{
    const int h = blockIdx.x;
    const int b = blockIdx.y;
    const int dir = blockIdx.z;
    const int tid = threadIdx.x;
    const int off = tid * 16;

    float hr[16];
#pragma unroll
    for (int i = 0; i < 16; i++) hr[i] = 0.f;

    for (int seg = 0; seg < SSEG; seg++) {
        size_t base = SEGIDX(dir, b, seg, h) * (size_t)(HEADDIM * DSTATE) + off;
        float* hin = g_hin + base;
#pragma unroll
        for (int i = 0; i < 16; i++) hin[i] = hr[i];
        float aend = g_cump[dir][(size_t)(b * LSEQ + seg * TSEG + TSEG - 1) * NHEADS + h];
        const float* hend = g_hseg + base;
#pragma unroll
        for (int i = 0; i < 16; i++) hr[i] = fmaf(aend, hr[i], hend[i]);
    }
}

// ---------------- SSD pass 3: Y = (C@B^T ∘ M)@X + (ahat∘C)@h_in + D*x ---------
__global__ __launch_bounds__(256)
void ssd_y(const float* __restrict__ D0, const float* __restrict__ D1)
{
    extern __shared__ float sm[];
    float* Cs  = sm;
    float* Bsm = sm + 4608;        // later overwritten with P
    float* Xs  = sm + 2 * 4608;
    float* Hs  = sm + 3 * 4608;
    float* Ms  = sm + 4 * 4608;
    __shared__ float das[64], dts_[64], ahat_[64];

    const int h = blockIdx.x;
    const int b = blockIdx.y / SSEG;
    const int ch = blockIdx.y % SSEG;
    const int dir = blockIdx.z;
    const int tid = threadIdx.x;
    const int t0 = b * LSEQ + ch * TSEG;
    const float* xbc = g_xbc[dir];
    const float Dh = (dir ? D1 : D0)[h];

    for (int i = tid; i < 1024; i += 256) {
        int r = i >> 4, c4 = (i & 15) * 4;
        size_t row = (size_t)(t0 + r) * CONVCH;
        *(float4*)&Bsm[r * 72 + c4] = *(const float4*)&xbc[row + DINNER + c4];
        *(float4*)&Cs [r * 72 + c4] = *(const float4*)&xbc[row + DINNER + DSTATE + c4];
        *(float4*)&Xs [r * 72 + c4] = *(const float4*)&xbc[row + h * HEADDIM + c4];
    }
    {
        const float* hin = g_hin + SEGIDX(dir, b, ch, h) * (size_t)(HEADDIM * DSTATE);
        for (int i = tid; i < 1024; i += 256) {
            int r = i >> 4, c4 = (i & 15) * 4;
            *(float4*)&Hs[r * 72 + c4] = *(const float4*)&hin[r * 64 + c4];
        }
    }
    if (tid < 64) {
        das[tid]  = g_dA[dir][(size_t)(t0 + tid) * NHEADS + h];
        dts_[tid] = g_dt[dir][(size_t)(t0 + tid) * NHEADS + h];
        ahat_[tid] = g_cump[dir][(size_t)(t0 + tid) * NHEADS + h];
    }
    for (int i = tid; i < 4608; i += 256) Ms[i] = 0.f;
    __syncthreads();

    // build decay matrix M by column recurrence (underflow -> 0 is exact)
    if (tid < 64) {
        int s = tid;
        float m = dts_[s];
        Ms[s * 72 + s] = m;
        for (int t = s + 1; t < 64; t++) {
            m *= das[t];
            Ms[t * 72 + s] = m;
        }
    }
    __syncthreads();

    const int wid = tid >> 5, lane = tid & 31, fg = lane >> 2, fc = lane & 3;
    const int m0 = (wid & 3) * 16, n0w = (wid >> 2) * 32;

    // GEMM1: G[t,s] = sum_n C[t,n] * B[s,n]
    float accg[4][4];
#pragma unroll
    for (int i = 0; i < 4; i++)
#pragma unroll
        for (int j = 0; j < 4; j++) accg[i][j] = 0.f;
    wgemm64<0, 0>(accg, Cs, Bsm, m0, n0w, fg, fc);
    __syncthreads();   // everyone done reading Bsm & Cs

    // P = G ∘ M into Bsm; Ca = ahat∘C in place
#pragma unroll
    for (int in = 0; in < 4; in++) {
        int s = n0w + in * 8 + 2 * fc;
        int t = m0 + fg;
        Bsm[t * 72 + s]     = accg[in][0] * Ms[t * 72 + s];
        Bsm[t * 72 + s + 1] = accg[in][1] * Ms[t * 72 + s + 1];
        Bsm[(t + 8) * 72 + s]     = accg[in][2] * Ms[(t + 8) * 72 + s];
        Bsm[(t + 8) * 72 + s + 1] = accg[in][3] * Ms[(t + 8) * 72 + s + 1];
    }
    for (int i = tid; i < 4096; i += 256) {
        int t = i >> 6, n = i & 63;
        Cs[t * 72 + n] *= ahat_[t];
    }
    __syncthreads();

    // GEMM2: Y = P@X + Ca@Hin
    float accy[4][4];
#pragma unroll
    for (int i = 0; i < 4; i++)
#pragma unroll
        for (int j = 0; j < 4; j++) accy[i][j] = 0.f;
    wgemm64<0, 1>(accy, Bsm, Xs, m0, n0w, fg, fc);
    wgemm64<0, 1>(accy, Cs, Hs, m0, n0w, fg, fc);

    // epilogue: + D*x, write y
    float* yout = g_y[dir];
#pragma unroll
    for (int in = 0; in < 4; in++) {
        int p = n0w + in * 8 + 2 * fc;
#pragma unroll
        for (int rr = 0; rr < 2; rr++) {
            int t = m0 + fg + rr * 8;
            float x0 = Xs[t * 72 + p];
            float x1 = Xs[t * 72 + p + 1];
            size_t idx = (size_t)(t0 + t) * DINNER + h * HEADDIM + p;
            yout[idx]     = accy[in][2 * rr + 0] + Dh * x0;
            yout[idx + 1] = accy[in][2 * rr + 1] + Dh * x1;
        }
    }
}

// ---------------- gated RMSNorm ----------------
__global__ __launch_bounds__(256)
void gated_norm(const float* __restrict__ nw0, const float* __restrict__ nw1)
{
    const int dir = blockIdx.y;
    const int row = blockIdx.x;
    const float* nw = dir ? nw1 : nw0;
    const float* y = g_y[dir] + (size_t)row * DINNER;
    const float* z = g_zx[dir] + (size_t)row * DPROJ;
    float* o = g_gn[dir] + (size_t)row * DINNER;

    float vals[8];
    float ss = 0.f;
#pragma unroll
    for (int i = 0; i < 8; i++) {
        int c = threadIdx.x + i * 256;
        float zz = z[c];
        float g = y[c] * (zz / (1.f + expf(-zz)));
        vals[i] = g;
        ss = fmaf(g, g, ss);
    }
#pragma unroll
    for (int o2 = 16; o2; o2 >>= 1) ss += __shfl_xor_sync(0xffffffffu, ss, o2);
    __shared__ float red[8];
    if ((threadIdx.x & 31) == 0) red[threadIdx.x >> 5] = ss;
    __syncthreads();
    float tot = red[0] + red[1] + red[2] + red[3] + red[4] + red[5] + red[6] + red[7];
    float scale = rsqrtf(tot * (1.f / DINNER) + 1e-5f);
#pragma unroll
    for (int i = 0; i < 8; i++) {
        int c = threadIdx.x + i * 256;
        o[c] = vals[i] * scale * nw[c];
    }
}

// ---------------- launch ----------------
extern "C" void kernel_launch(void* const* d_in, const int* in_sizes, int n_in,
                              void* d_out, int out_size)
{
    (void)in_sizes; (void)n_in; (void)out_size;
    const float* x      = (const float*)d_in[0];
    const float* fWin   = (const float*)d_in[1];
    const float* fconvw = (const float*)d_in[2];
    const float* fconvb = (const float*)d_in[3];
    const float* fdtb   = (const float*)d_in[4];
    const float* fAlog  = (const float*)d_in[5];
    const float* fD     = (const float*)d_in[6];
    const float* fnormw = (const float*)d_in[7];
    const float* fWout  = (const float*)d_in[8];
    const float* bWin   = (const float*)d_in[9];
    const float* bconvw = (const float*)d_in[10];
    const float* bconvb = (const float*)d_in[11];
    const float* bdtb   = (const float*)d_in[12];
    const float* bAlog  = (const float*)d_in[13];
    const float* bD     = (const float*)d_in[14];
    const float* bnormw = (const float*)d_in[15];
    const float* bWout  = (const float*)d_in[16];
    const float* Wo     = (const float*)d_in[17];
    const float* bo     = (const float*)d_in[18];
    float* out = (float*)d_out;

    static int smem_set = 0;
    if (!smem_set) {
        cudaFuncSetAttribute(ssd_y, cudaFuncAttributeMaxDynamicSharedMemorySize, 5 * 4608 * 4);
        smem_set = 1;
    }

    float *zx, *gn, *cat;
    cudaGetSymbolAddress((void**)&zx, g_zx);
    cudaGetSymbolAddress((void**)&gn, g_gn);
    cudaGetSymbolAddress((void**)&cat, g_cat);
    float* zx0 = zx;
    float* zx1 = zx + (size_t)NTOK * DPROJ;
    float* gn0 = gn;
    float* gn1 = gn + (size_t)NTOK * DINNER;

    // 1) input projections
    dim3 g1((DPROJ + 127) / 128, NTOK / 128);
    tgemm<<<g1, 256>>>(x, DMODEL, fWin, DPROJ, zx0, DPROJ, 0,
                       NTOK, DPROJ, DMODEL, 0, 0, nullptr);
    tgemm<<<g1, 256>>>(x, DMODEL, bWin, DPROJ, zx1, DPROJ, 0,
                       NTOK, DPROJ, DMODEL, 1, 0, nullptr);

    // 2) causal conv + silu + dt/dA
    conv_silu_dt<<<dim3(LSEQ, BSZ, 2), 256>>>(fconvw, fconvb, fdtb, fAlog,
                                              bconvw, bconvb, bdtb, bAlog);

    // 3) SSD tensor-core scan
    ssd_state<<<dim3(NHEADS, BSZ * SSEG, 2), 256>>>();
    ssd_combine<<<dim3(NHEADS, BSZ, 2), 256>>>();
    ssd_y<<<dim3(NHEADS, BSZ * SSEG, 2), 256, 5 * 4608 * 4>>>(fD, bD);

    // 4) gated RMSNorm
    gated_norm<<<dim3(NTOK, 2), 256>>>(fnormw, bnormw);

    // 5) per-direction output projections
    dim3 g2(DMODEL / 128, NTOK / 128);
    tgemm<<<g2, 256>>>(gn0, DINNER, fWout, DMODEL, cat, 2 * DMODEL, 0,
                       NTOK, DMODEL, DINNER, 0, 0, nullptr);
    tgemm<<<g2, 256>>>(gn1, DINNER, bWout, DMODEL, cat, 2 * DMODEL, DMODEL,
                       NTOK, DMODEL, DINNER, 0, 1, nullptr);

    // 6) final projection + bias
    tgemm<<<g2, 256>>>(cat, 2 * DMODEL, Wo, DMODEL, out, DMODEL, 0,
                       NTOK, DMODEL, 2 * DMODEL, 0, 0, bo);
}